// round 14
// baseline (speedup 1.0000x reference)
#include <cuda_runtime.h>
#include <cuda_bf16.h>
#include <math.h>
#include <stdint.h>

// ---------------------------------------------------------------------------
// CFNO folded: patchify(16x16) -> FFT(256) -> complex linear -> IFFT(16).real
// -> 1x1 conv == y = p @ G + g0 (real G[256][16]); then GroupNorm(8,16).
//
// Main kernel: HMMA (mma.sync.m16n8k16 bf16) with exact hi/lo split:
//   x = hi + lo (hi = fp32 top-16 bits, exact bf16; lo = x - hi)
//   y = Ah*Bh + Al*Bh + Ah*Bl   (AlBl ~2^-16 dropped)
// A gmem -> registers in fragment layout; B fragments via __ldg (L1-resident).
// ---------------------------------------------------------------------------

#define PI_D 3.141592653589793238462643383279502884

__device__ float g_g0[16];
__device__ __align__(16) uint2 g_Bfh[1024]; // B fragments hi: [kk][lane][nh]
__device__ __align__(16) uint2 g_Bfl[1024]; // B fragments lo
__device__ float g_Y[8 * 16 * 128 * 128];   // 8 MB, (b,e,h,w)
__device__ float g_psum[8 * 16 * 128];      // [b][e][hr]
__device__ float g_psq[8 * 16 * 128];
__device__ float g_sc[128];                 // per (b*16+e) scale
__device__ float g_sh[128];                 // per (b*16+e) shift

// ---------------------------------------------------------------------------
// Kernel 1: fold chain into B[256][16] and emit m16n8k16 B fragments.
// 1024 threads: DFT k-loop split 4 ways (ks = tid&3), shfl-quad reduce.
// ---------------------------------------------------------------------------
__global__ void __launch_bounds__(1024) precompute_kernel(
        const float* __restrict__ wr, const float* __restrict__ wi,
        const float* __restrict__ br, const float* __restrict__ bi,
        const float* __restrict__ cw, const float* __restrict__ cb) {
    __shared__ float cosT[256], sinT[256];
    __shared__ float swr[16 * 257], swi[16 * 257];
    __shared__ float sCR[256], sCI[256];
    __shared__ float sMR[256], sMI[256];
    __shared__ float sB[256];
    const int tid = threadIdx.x;

    if (tid < 256) {
        double s, c;
        sincos(2.0 * PI_D * (double)tid / 256.0, &s, &c);
        cosT[tid] = (float)c; sinT[tid] = (float)s;
    }
    for (int i = tid; i < 4096; i += 1024) {
        int d = i >> 8, k = i & 255;
        swr[d * 257 + k] = wr[i];
        swi[d * 257 + k] = wi[i];
    }
    __syncthreads();

    if (tid < 256) {   // CR/CI
        const int dd = tid >> 4, e = tid & 15;
        float cr = 0.f, ci = 0.f;
#pragma unroll
        for (int m = 0; m < 16; m++) {
            int t = ((dd * m) & 15) << 4;
            float w = cw[e * 16 + m];
            cr += w * cosT[t];
            ci += w * sinT[t];
        }
        sCR[dd * 16 + e] = cr; sCI[dd * 16 + e] = ci;
    }
    {   // MR/MI: jl = tid>>6, d = (tid>>2)&15, ks = tid&3
        const int jl = tid >> 6, d = (tid >> 2) & 15, ks = tid & 3;
        const int j = (blockIdx.x << 4) + jl;
        const float* a  = swr + d * 257;
        const float* bb = swi + d * 257;
        const int k0 = ks << 6;
        float mr0 = 0.f, mi0 = 0.f, mr1 = 0.f, mi1 = 0.f;
        float mr2 = 0.f, mi2 = 0.f, mr3 = 0.f, mi3 = 0.f;
        for (int k = k0; k < k0 + 64; k += 4) {
            int t0 = (k * j) & 255, t1 = (t0 + j) & 255;
            int t2 = (t1 + j) & 255, t3 = (t2 + j) & 255;
            float c0 = cosT[t0], s0 = sinT[t0], a0 = a[k],     b0 = bb[k];
            float c1 = cosT[t1], s1 = sinT[t1], a1 = a[k + 1], b1 = bb[k + 1];
            float c2 = cosT[t2], s2 = sinT[t2], a2 = a[k + 2], b2 = bb[k + 2];
            float c3 = cosT[t3], s3 = sinT[t3], a3 = a[k + 3], b3 = bb[k + 3];
            mr0 += a0 * c0 + b0 * s0;  mi0 += b0 * c0 - a0 * s0;
            mr1 += a1 * c1 + b1 * s1;  mi1 += b1 * c1 - a1 * s1;
            mr2 += a2 * c2 + b2 * s2;  mi2 += b2 * c2 - a2 * s2;
            mr3 += a3 * c3 + b3 * s3;  mi3 += b3 * c3 - a3 * s3;
        }
        float mr = (mr0 + mr1) + (mr2 + mr3);
        float mi = (mi0 + mi1) + (mi2 + mi3);
        mr += __shfl_xor_sync(0xffffffffu, mr, 1);
        mi += __shfl_xor_sync(0xffffffffu, mi, 1);
        mr += __shfl_xor_sync(0xffffffffu, mr, 2);
        mi += __shfl_xor_sync(0xffffffffu, mi, 2);
        if (ks == 0) { sMR[jl * 16 + d] = mr; sMI[jl * 16 + d] = mi; }
    }
    __syncthreads();
    if (tid < 256) {
        const int jl = tid >> 4, e = tid & 15;
        float g = 0.f;
#pragma unroll
        for (int d = 0; d < 16; d++)
            g += sMR[jl * 16 + d] * sCR[d * 16 + e] - sMI[jl * 16 + d] * sCI[d * 16 + e];
        sB[jl * 16 + e] = g * (1.0f / 64.0f);
    }
    __syncthreads();
    if (tid < 64) {   // emit fragments for kk = blockIdx.x; layout [kk][lane][nh]
        const int lane = tid & 31, nh = tid >> 5;
        const int q = lane & 3, gg = lane >> 2;
        const int n = nh * 8 + gg;
        const int j0 = 2 * q;
        float B0 = sB[(j0)     * 16 + n];
        float B1 = sB[(j0 + 1) * 16 + n];
        float B2 = sB[(j0 + 8) * 16 + n];
        float B3 = sB[(j0 + 9) * 16 + n];
        uint32_t u0 = __float_as_uint(B0), u1 = __float_as_uint(B1);
        uint32_t u2 = __float_as_uint(B2), u3 = __float_as_uint(B3);
        uint2 h, lo;
        h.x = __byte_perm(u0, u1, 0x7632);
        h.y = __byte_perm(u2, u3, 0x7632);
        float l0 = B0 - __uint_as_float(u0 & 0xFFFF0000u);
        float l1 = B1 - __uint_as_float(u1 & 0xFFFF0000u);
        float l2 = B2 - __uint_as_float(u2 & 0xFFFF0000u);
        float l3 = B3 - __uint_as_float(u3 & 0xFFFF0000u);
        asm("cvt.rn.bf16x2.f32 %0, %1, %2;" : "=r"(lo.x) : "f"(l1), "f"(l0));
        asm("cvt.rn.bf16x2.f32 %0, %1, %2;" : "=r"(lo.y) : "f"(l3), "f"(l2));
        const int t = (blockIdx.x << 6) + lane * 2 + nh;
        g_Bfh[t] = h;
        g_Bfl[t] = lo;
    }
    if (blockIdx.x == 0 && tid < 16) {
        float acc = cb[tid];
        for (int m = 0; m < 16; m++) {
            float b0 = 0.f;
            for (int d = 0; d < 16; d++) {
                int t = ((d * m) & 15) << 4;
                b0 += br[d] * cosT[t] - bi[d] * sinT[t];
            }
            acc += cw[tid * 16 + m] * b0 * 0.25f;
        }
        g_g0[tid] = acc;
    }
}

// pad launch so main_kernel lands on the ncu-profiled launch index (3)
__global__ void pad_kernel() {}

// ---------------------------------------------------------------------------
// Main kernel helpers
// ---------------------------------------------------------------------------
__device__ __forceinline__ void split_bf16(float2 f, uint32_t& h, uint32_t& lo) {
    uint32_t u0 = __float_as_uint(f.x), u1 = __float_as_uint(f.y);
    h = __byte_perm(u0, u1, 0x7632);
    float l0 = f.x - __uint_as_float(u0 & 0xFFFF0000u);
    float l1 = f.y - __uint_as_float(u1 & 0xFFFF0000u);
    asm("cvt.rn.bf16x2.f32 %0, %1, %2;" : "=r"(lo) : "f"(l1), "f"(l0));
}
__device__ __forceinline__ void mma16816(float* c, const uint32_t* a, uint32_t bx, uint32_t by) {
    asm("mma.sync.aligned.m16n8k16.row.col.f32.bf16.bf16.f32 "
        "{%0,%1,%2,%3}, {%4,%5,%6,%7}, {%8,%9}, {%0,%1,%2,%3};"
        : "+f"(c[0]), "+f"(c[1]), "+f"(c[2]), "+f"(c[3])
        : "r"(a[0]), "r"(a[1]), "r"(a[2]), "r"(a[3]), "r"(bx), "r"(by));
}

// ---------------------------------------------------------------------------
// Kernel 2 (hot): 1024 blocks x 256 threads (8 warps). Block = one patch row;
// warp = 16 patches. A loaded straight from gmem into fragment layout with
// prefetch distance 2; B fragments via __ldg from global (L1-resident 32KB).
// ---------------------------------------------------------------------------
#define SYP 132

__global__ void __launch_bounds__(256) main_kernel(const float* __restrict__ x) {
    __shared__ float sY[16 * SYP];
    const int tid = threadIdx.x;
    const int w = tid >> 5, lane = tid & 31;
    const int b  = blockIdx.x >> 7;
    const int hr = blockIdx.x & 127;

    const int g = lane >> 2, q = lane & 3;
    const float* aptr = x + (((size_t)b) << 22) + (((size_t)hr) << 15)
                          + (w * 16 + g) * 16 + q * 2;
    const uint4* bfh = ((const uint4*)g_Bfh) + lane;
    const uint4* bfl = ((const uint4*)g_Bfl) + lane;

    float acc0[4] = {0.f, 0.f, 0.f, 0.f};
    float acc1[4] = {0.f, 0.f, 0.f, 0.f};

    float2 f[2][4];
#pragma unroll
    for (int p = 0; p < 2; p++) {
        const float* rp = aptr + (p << 11);
        f[p][0] = *(const float2*)(rp);
        f[p][1] = *(const float2*)(rp + 8);
        f[p][2] = *(const float2*)(rp + 128);
        f[p][3] = *(const float2*)(rp + 136);
    }

#pragma unroll 4
    for (int kk = 0; kk < 16; kk++) {
        const int cur = kk & 1;
        uint32_t ah[4], al[4];
        split_bf16(f[cur][0], ah[0], al[0]);   // row g,   k-low
        split_bf16(f[cur][2], ah[1], al[1]);   // row g+8, k-low
        split_bf16(f[cur][1], ah[2], al[2]);   // row g,   k-high
        split_bf16(f[cur][3], ah[3], al[3]);   // row g+8, k-high

        if (kk < 14) {
            const float* np = aptr + ((kk + 2) << 11);
            f[cur][0] = *(const float2*)(np);
            f[cur][1] = *(const float2*)(np + 8);
            f[cur][2] = *(const float2*)(np + 128);
            f[cur][3] = *(const float2*)(np + 136);
        }

        uint4 vh = __ldg(bfh + (kk << 5));
        uint4 vl = __ldg(bfl + (kk << 5));

        mma16816(acc0, ah, vh.x, vh.y);
        mma16816(acc1, ah, vh.z, vh.w);
        mma16816(acc0, al, vh.x, vh.y);
        mma16816(acc1, al, vh.z, vh.w);
        mma16816(acc0, ah, vl.x, vl.y);
        mma16816(acc1, ah, vl.z, vl.w);
    }

    // scatter C fragments to sY[e][p]
    {
        const int p_lo = w * 16 + g, p_hi = p_lo + 8;
        sY[(2 * q + 0) * SYP + p_lo] = acc0[0];
        sY[(2 * q + 1) * SYP + p_lo] = acc0[1];
        sY[(2 * q + 0) * SYP + p_hi] = acc0[2];
        sY[(2 * q + 1) * SYP + p_hi] = acc0[3];
        sY[(8 + 2 * q) * SYP + p_lo] = acc1[0];
        sY[(9 + 2 * q) * SYP + p_lo] = acc1[1];
        sY[(8 + 2 * q) * SYP + p_hi] = acc1[2];
        sY[(9 + 2 * q) * SYP + p_hi] = acc1[3];
    }
    __syncthreads();

    // staging: thread -> channel e = tid>>4, 8 consecutive patches
    {
        const int e = tid >> 4, i2 = tid & 15;
        const float g0v = g_g0[e];
        float v[8];
        float4 va = *(const float4*)&sY[e * SYP + i2 * 8];
        float4 vb = *(const float4*)&sY[e * SYP + i2 * 8 + 4];
        v[0] = va.x + g0v; v[1] = va.y + g0v; v[2] = va.z + g0v; v[3] = va.w + g0v;
        v[4] = vb.x + g0v; v[5] = vb.y + g0v; v[6] = vb.z + g0v; v[7] = vb.w + g0v;

        float s = 0.f, qq = 0.f;
#pragma unroll
        for (int j = 0; j < 8; j++) { s += v[j]; qq += v[j] * v[j]; }

        float* dst = &g_Y[(((size_t)(b * 16 + e)) << 14) + (hr << 7) + i2 * 8];
        *(float4*)dst = make_float4(v[0], v[1], v[2], v[3]);
        *(float4*)(dst + 4) = make_float4(v[4], v[5], v[6], v[7]);

#pragma unroll
        for (int off = 8; off; off >>= 1) {
            s  += __shfl_down_sync(0xffffffffu, s, off, 16);
            qq += __shfl_down_sync(0xffffffffu, qq, off, 16);
        }
        if (i2 == 0) {
            g_psum[(b * 16 + e) * 128 + hr] = s;
            g_psq[(b * 16 + e) * 128 + hr] = qq;
        }
    }
}

// ---------------------------------------------------------------------------
// Kernel 3: stats + per-channel scale/shift. 64 blocks x 128 threads.
// ---------------------------------------------------------------------------
__global__ void __launch_bounds__(128) stats_kernel(const float* __restrict__ gamma,
                                                    const float* __restrict__ beta) {
    __shared__ float ss[4], sq[4];
    const int bg = blockIdx.x;
    const int b = bg >> 3, grp = bg & 7;
    const int tid = threadIdx.x;
    const int base0 = (b * 16 + grp * 2) * 128;
    const int base1 = base0 + 128;
    float s = g_psum[base0 + tid] + g_psum[base1 + tid];
    float q = g_psq[base0 + tid]  + g_psq[base1 + tid];
#pragma unroll
    for (int off = 16; off; off >>= 1) {
        s += __shfl_down_sync(0xffffffffu, s, off);
        q += __shfl_down_sync(0xffffffffu, q, off);
    }
    const int lane = tid & 31, wrp = tid >> 5;
    if (lane == 0) { ss[wrp] = s; sq[wrp] = q; }
    __syncthreads();
    if (tid < 2) {
        float st = ss[0] + ss[1] + ss[2] + ss[3];
        float qt = sq[0] + sq[1] + sq[2] + sq[3];
        const float invN = 1.0f / 32768.0f;
        float mean = st * invN;
        float var  = qt * invN - mean * mean;
        float istd = rsqrtf(var + 1e-5f);
        const int e = grp * 2 + tid;
        float sc = istd * gamma[e];
        g_sc[b * 16 + e] = sc;
        g_sh[b * 16 + e] = beta[e] - mean * sc;
    }
}

// ---------------------------------------------------------------------------
// Kernel 4: normalize via table lookup. 524288 threads, one float4 each.
// ---------------------------------------------------------------------------
__global__ void __launch_bounds__(512) finalize_kernel(float* __restrict__ out) {
    const int idx = blockIdx.x * 512 + threadIdx.x;       // 524288 float4
    float4 v = ((const float4*)g_Y)[idx];
    const int plane = idx >> 12;                          // = b*16 + e
    const float sc = g_sc[plane];
    const float sh = g_sh[plane];
    v.x = v.x * sc + sh; v.y = v.y * sc + sh;
    v.z = v.z * sc + sh; v.w = v.w * sc + sh;
    ((float4*)out)[idx] = v;
}

extern "C" void kernel_launch(void* const* d_in, const int* in_sizes, int n_in,
                              void* d_out, int out_size) {
    const float* x     = (const float*)d_in[0];
    const float* wr    = (const float*)d_in[1];
    const float* wi    = (const float*)d_in[2];
    const float* br    = (const float*)d_in[3];
    const float* bi    = (const float*)d_in[4];
    const float* cw    = (const float*)d_in[5];
    const float* cb    = (const float*)d_in[6];
    const float* gamma = (const float*)d_in[7];
    const float* beta  = (const float*)d_in[8];
    float* out = (float*)d_out;

    precompute_kernel<<<16, 1024>>>(wr, wi, br, bi, cw, cb);
    pad_kernel<<<1, 32>>>();           // shift main_kernel to profiled launch index 3
    pad_kernel<<<1, 32>>>();
    main_kernel<<<1024, 256>>>(x);
    stats_kernel<<<64, 128>>>(gamma, beta);
    finalize_kernel<<<1024, 512>>>(out);
}

// round 15
// speedup vs baseline: 1.0338x; 1.0338x over previous
#include <cuda_runtime.h>
#include <cuda_bf16.h>
#include <math.h>
#include <stdint.h>

// ---------------------------------------------------------------------------
// CFNO folded: patchify(16x16) -> FFT(256) -> complex linear -> IFFT(16).real
// -> 1x1 conv == y = p @ G + g0 (real G[256][16]); then GroupNorm(8,16).
//
// Main kernel: HMMA (mma.sync.m16n8k16 bf16) with exact hi/lo split:
//   x = hi + lo (hi = fp32 top-16 bits, exact bf16; lo = x - hi)
//   y = Ah*Bh + Al*Bh + Ah*Bl   (AlBl ~2^-16 dropped)
// A gmem -> registers in fragment layout; B fragments via __ldg (L1-resident).
// 2048 blocks x 128 threads (half patch-row each) for occupancy + small tail.
// ---------------------------------------------------------------------------

#define PI_D 3.141592653589793238462643383279502884

__device__ float g_g0[16];
__device__ __align__(16) uint2 g_Bfh[1024]; // B fragments hi: [kk][lane][nh]
__device__ __align__(16) uint2 g_Bfl[1024]; // B fragments lo
__device__ float g_Y[8 * 16 * 128 * 128];   // 8 MB, (b,e,h,w)
__device__ float g_psum[8 * 16 * 256];      // [b][e][halfrow]
__device__ float g_psq[8 * 16 * 256];
__device__ float g_sc[128];                 // per (b*16+e) scale
__device__ float g_sh[128];                 // per (b*16+e) shift

// ---------------------------------------------------------------------------
// Kernel 1: fold chain into B[256][16] and emit m16n8k16 B fragments.
// ---------------------------------------------------------------------------
__global__ void __launch_bounds__(1024) precompute_kernel(
        const float* __restrict__ wr, const float* __restrict__ wi,
        const float* __restrict__ br, const float* __restrict__ bi,
        const float* __restrict__ cw, const float* __restrict__ cb) {
    __shared__ float cosT[256], sinT[256];
    __shared__ float swr[16 * 257], swi[16 * 257];
    __shared__ float sCR[256], sCI[256];
    __shared__ float sMR[256], sMI[256];
    __shared__ float sB[256];
    const int tid = threadIdx.x;

    if (tid < 256) {
        double s, c;
        sincos(2.0 * PI_D * (double)tid / 256.0, &s, &c);
        cosT[tid] = (float)c; sinT[tid] = (float)s;
    }
    for (int i = tid; i < 4096; i += 1024) {
        int d = i >> 8, k = i & 255;
        swr[d * 257 + k] = wr[i];
        swi[d * 257 + k] = wi[i];
    }
    __syncthreads();

    if (tid < 256) {   // CR/CI
        const int dd = tid >> 4, e = tid & 15;
        float cr = 0.f, ci = 0.f;
#pragma unroll
        for (int m = 0; m < 16; m++) {
            int t = ((dd * m) & 15) << 4;
            float w = cw[e * 16 + m];
            cr += w * cosT[t];
            ci += w * sinT[t];
        }
        sCR[dd * 16 + e] = cr; sCI[dd * 16 + e] = ci;
    }
    {   // MR/MI: jl = tid>>6, d = (tid>>2)&15, ks = tid&3
        const int jl = tid >> 6, d = (tid >> 2) & 15, ks = tid & 3;
        const int j = (blockIdx.x << 4) + jl;
        const float* a  = swr + d * 257;
        const float* bb = swi + d * 257;
        const int k0 = ks << 6;
        float mr0 = 0.f, mi0 = 0.f, mr1 = 0.f, mi1 = 0.f;
        float mr2 = 0.f, mi2 = 0.f, mr3 = 0.f, mi3 = 0.f;
        for (int k = k0; k < k0 + 64; k += 4) {
            int t0 = (k * j) & 255, t1 = (t0 + j) & 255;
            int t2 = (t1 + j) & 255, t3 = (t2 + j) & 255;
            float c0 = cosT[t0], s0 = sinT[t0], a0 = a[k],     b0 = bb[k];
            float c1 = cosT[t1], s1 = sinT[t1], a1 = a[k + 1], b1 = bb[k + 1];
            float c2 = cosT[t2], s2 = sinT[t2], a2 = a[k + 2], b2 = bb[k + 2];
            float c3 = cosT[t3], s3 = sinT[t3], a3 = a[k + 3], b3 = bb[k + 3];
            mr0 += a0 * c0 + b0 * s0;  mi0 += b0 * c0 - a0 * s0;
            mr1 += a1 * c1 + b1 * s1;  mi1 += b1 * c1 - a1 * s1;
            mr2 += a2 * c2 + b2 * s2;  mi2 += b2 * c2 - a2 * s2;
            mr3 += a3 * c3 + b3 * s3;  mi3 += b3 * c3 - a3 * s3;
        }
        float mr = (mr0 + mr1) + (mr2 + mr3);
        float mi = (mi0 + mi1) + (mi2 + mi3);
        mr += __shfl_xor_sync(0xffffffffu, mr, 1);
        mi += __shfl_xor_sync(0xffffffffu, mi, 1);
        mr += __shfl_xor_sync(0xffffffffu, mr, 2);
        mi += __shfl_xor_sync(0xffffffffu, mi, 2);
        if (ks == 0) { sMR[jl * 16 + d] = mr; sMI[jl * 16 + d] = mi; }
    }
    __syncthreads();
    if (tid < 256) {
        const int jl = tid >> 4, e = tid & 15;
        float g = 0.f;
#pragma unroll
        for (int d = 0; d < 16; d++)
            g += sMR[jl * 16 + d] * sCR[d * 16 + e] - sMI[jl * 16 + d] * sCI[d * 16 + e];
        sB[jl * 16 + e] = g * (1.0f / 64.0f);
    }
    __syncthreads();
    if (tid < 64) {   // emit fragments for kk = blockIdx.x; layout [kk][lane][nh]
        const int lane = tid & 31, nh = tid >> 5;
        const int q = lane & 3, gg = lane >> 2;
        const int n = nh * 8 + gg;
        const int j0 = 2 * q;
        float B0 = sB[(j0)     * 16 + n];
        float B1 = sB[(j0 + 1) * 16 + n];
        float B2 = sB[(j0 + 8) * 16 + n];
        float B3 = sB[(j0 + 9) * 16 + n];
        uint32_t u0 = __float_as_uint(B0), u1 = __float_as_uint(B1);
        uint32_t u2 = __float_as_uint(B2), u3 = __float_as_uint(B3);
        uint2 h, lo;
        h.x = __byte_perm(u0, u1, 0x7632);
        h.y = __byte_perm(u2, u3, 0x7632);
        float l0 = B0 - __uint_as_float(u0 & 0xFFFF0000u);
        float l1 = B1 - __uint_as_float(u1 & 0xFFFF0000u);
        float l2 = B2 - __uint_as_float(u2 & 0xFFFF0000u);
        float l3 = B3 - __uint_as_float(u3 & 0xFFFF0000u);
        asm("cvt.rn.bf16x2.f32 %0, %1, %2;" : "=r"(lo.x) : "f"(l1), "f"(l0));
        asm("cvt.rn.bf16x2.f32 %0, %1, %2;" : "=r"(lo.y) : "f"(l3), "f"(l2));
        const int t = (blockIdx.x << 6) + lane * 2 + nh;
        g_Bfh[t] = h;
        g_Bfl[t] = lo;
    }
    if (blockIdx.x == 0 && tid < 16) {
        float acc = cb[tid];
        for (int m = 0; m < 16; m++) {
            float b0 = 0.f;
            for (int d = 0; d < 16; d++) {
                int t = ((d * m) & 15) << 4;
                b0 += br[d] * cosT[t] - bi[d] * sinT[t];
            }
            acc += cw[tid * 16 + m] * b0 * 0.25f;
        }
        g_g0[tid] = acc;
    }
}

// ---------------------------------------------------------------------------
// Main kernel helpers
// ---------------------------------------------------------------------------
__device__ __forceinline__ void split_bf16(float2 f, uint32_t& h, uint32_t& lo) {
    uint32_t u0 = __float_as_uint(f.x), u1 = __float_as_uint(f.y);
    h = __byte_perm(u0, u1, 0x7632);
    float l0 = f.x - __uint_as_float(u0 & 0xFFFF0000u);
    float l1 = f.y - __uint_as_float(u1 & 0xFFFF0000u);
    asm("cvt.rn.bf16x2.f32 %0, %1, %2;" : "=r"(lo) : "f"(l1), "f"(l0));
}
__device__ __forceinline__ void mma16816(float* c, const uint32_t* a, uint32_t bx, uint32_t by) {
    asm("mma.sync.aligned.m16n8k16.row.col.f32.bf16.bf16.f32 "
        "{%0,%1,%2,%3}, {%4,%5,%6,%7}, {%8,%9}, {%0,%1,%2,%3};"
        : "+f"(c[0]), "+f"(c[1]), "+f"(c[2]), "+f"(c[3])
        : "r"(a[0]), "r"(a[1]), "r"(a[2]), "r"(a[3]), "r"(bx), "r"(by));
}

// ---------------------------------------------------------------------------
// Kernel 2 (hot): 2048 blocks x 128 threads (4 warps). Block = HALF patch row
// (64 patches); warp = 16 patches. A gmem -> fragment registers, prefetch 2;
// B fragments via __ldg (L1-resident 32KB).
// ---------------------------------------------------------------------------
#define SYP 68

__global__ void __launch_bounds__(128, 10) main_kernel(const float* __restrict__ x) {
    __shared__ float sY[16 * SYP];
    const int tid = threadIdx.x;
    const int w = tid >> 5, lane = tid & 31;
    const int b    = blockIdx.x >> 8;
    const int sub  = blockIdx.x & 255;
    const int hr   = sub >> 1;
    const int half = sub & 1;

    const int g = lane >> 2, q = lane & 3;
    const float* aptr = x + (((size_t)b) << 22) + (((size_t)hr) << 15)
                          + (half << 10) + (w * 16 + g) * 16 + q * 2;
    const uint4* bfh = ((const uint4*)g_Bfh) + lane;
    const uint4* bfl = ((const uint4*)g_Bfl) + lane;

    float acc0[4] = {0.f, 0.f, 0.f, 0.f};
    float acc1[4] = {0.f, 0.f, 0.f, 0.f};

    float2 f[2][4];
#pragma unroll
    for (int p = 0; p < 2; p++) {
        const float* rp = aptr + (p << 11);
        f[p][0] = *(const float2*)(rp);
        f[p][1] = *(const float2*)(rp + 8);
        f[p][2] = *(const float2*)(rp + 128);
        f[p][3] = *(const float2*)(rp + 136);
    }

#pragma unroll 4
    for (int kk = 0; kk < 16; kk++) {
        const int cur = kk & 1;
        uint32_t ah[4], al[4];
        split_bf16(f[cur][0], ah[0], al[0]);   // row g,   k-low
        split_bf16(f[cur][2], ah[1], al[1]);   // row g+8, k-low
        split_bf16(f[cur][1], ah[2], al[2]);   // row g,   k-high
        split_bf16(f[cur][3], ah[3], al[3]);   // row g+8, k-high

        if (kk < 14) {
            const float* np = aptr + ((kk + 2) << 11);
            f[cur][0] = *(const float2*)(np);
            f[cur][1] = *(const float2*)(np + 8);
            f[cur][2] = *(const float2*)(np + 128);
            f[cur][3] = *(const float2*)(np + 136);
        }

        uint4 vh = __ldg(bfh + (kk << 5));
        uint4 vl = __ldg(bfl + (kk << 5));

        mma16816(acc0, ah, vh.x, vh.y);
        mma16816(acc1, ah, vh.z, vh.w);
        mma16816(acc0, al, vh.x, vh.y);
        mma16816(acc1, al, vh.z, vh.w);
        mma16816(acc0, ah, vl.x, vl.y);
        mma16816(acc1, ah, vl.z, vl.w);
    }

    // scatter C fragments to sY[e][p] (p local 0..63)
    {
        const int p_lo = w * 16 + g, p_hi = p_lo + 8;
        sY[(2 * q + 0) * SYP + p_lo] = acc0[0];
        sY[(2 * q + 1) * SYP + p_lo] = acc0[1];
        sY[(2 * q + 0) * SYP + p_hi] = acc0[2];
        sY[(2 * q + 1) * SYP + p_hi] = acc0[3];
        sY[(8 + 2 * q) * SYP + p_lo] = acc1[0];
        sY[(9 + 2 * q) * SYP + p_lo] = acc1[1];
        sY[(8 + 2 * q) * SYP + p_hi] = acc1[2];
        sY[(9 + 2 * q) * SYP + p_hi] = acc1[3];
    }
    __syncthreads();

    // staging: thread -> channel e = tid>>3, 8 consecutive patches
    {
        const int e = tid >> 3, i2 = tid & 7;
        const float g0v = __ldg(&g_g0[e]);
        float v[8];
        float4 va = *(const float4*)&sY[e * SYP + i2 * 8];
        float4 vb = *(const float4*)&sY[e * SYP + i2 * 8 + 4];
        v[0] = va.x + g0v; v[1] = va.y + g0v; v[2] = va.z + g0v; v[3] = va.w + g0v;
        v[4] = vb.x + g0v; v[5] = vb.y + g0v; v[6] = vb.z + g0v; v[7] = vb.w + g0v;

        float s = 0.f, qq = 0.f;
#pragma unroll
        for (int j = 0; j < 8; j++) { s += v[j]; qq += v[j] * v[j]; }

        float* dst = &g_Y[(((size_t)(b * 16 + e)) << 14) + (hr << 7) + (half << 6) + i2 * 8];
        *(float4*)dst = make_float4(v[0], v[1], v[2], v[3]);
        *(float4*)(dst + 4) = make_float4(v[4], v[5], v[6], v[7]);

#pragma unroll
        for (int off = 4; off; off >>= 1) {
            s  += __shfl_down_sync(0xffffffffu, s, off, 8);
            qq += __shfl_down_sync(0xffffffffu, qq, off, 8);
        }
        if (i2 == 0) {
            g_psum[(b * 16 + e) * 256 + sub] = s;
            g_psq[(b * 16 + e) * 256 + sub] = qq;
        }
    }
}

// ---------------------------------------------------------------------------
// Kernel 3: stats + per-channel scale/shift. 64 blocks x 256 threads.
// ---------------------------------------------------------------------------
__global__ void __launch_bounds__(256) stats_kernel(const float* __restrict__ gamma,
                                                    const float* __restrict__ beta) {
    __shared__ float ss[8], sq[8];
    const int bg = blockIdx.x;
    const int b = bg >> 3, grp = bg & 7;
    const int tid = threadIdx.x;
    const int base0 = (b * 16 + grp * 2) * 256;
    const int base1 = base0 + 256;
    float s = g_psum[base0 + tid] + g_psum[base1 + tid];
    float q = g_psq[base0 + tid]  + g_psq[base1 + tid];
#pragma unroll
    for (int off = 16; off; off >>= 1) {
        s += __shfl_down_sync(0xffffffffu, s, off);
        q += __shfl_down_sync(0xffffffffu, q, off);
    }
    const int lane = tid & 31, wrp = tid >> 5;
    if (lane == 0) { ss[wrp] = s; sq[wrp] = q; }
    __syncthreads();
    if (tid < 2) {
        float st = 0.f, qt = 0.f;
#pragma unroll
        for (int k = 0; k < 8; k++) { st += ss[k]; qt += sq[k]; }
        const float invN = 1.0f / 32768.0f;
        float mean = st * invN;
        float var  = qt * invN - mean * mean;
        float istd = rsqrtf(var + 1e-5f);
        const int e = grp * 2 + tid;
        float sc = istd * gamma[e];
        g_sc[b * 16 + e] = sc;
        g_sh[b * 16 + e] = beta[e] - mean * sc;
    }
}

// ---------------------------------------------------------------------------
// Kernel 4: normalize via table lookup; 2 independent float4 per thread.
// ---------------------------------------------------------------------------
__global__ void __launch_bounds__(512) finalize_kernel(float* __restrict__ out) {
    const int t = blockIdx.x * 512 + threadIdx.x;         // 262144 threads
    float4 v0 = ((const float4*)g_Y)[t];
    float4 v1 = ((const float4*)g_Y)[t + 262144];
    const int p0 = t >> 12, p1 = (t + 262144) >> 12;
    const float sc0 = g_sc[p0], sh0 = g_sh[p0];
    const float sc1 = g_sc[p1], sh1 = g_sh[p1];
    float4 o0, o1;
    o0.x = v0.x * sc0 + sh0; o0.y = v0.y * sc0 + sh0;
    o0.z = v0.z * sc0 + sh0; o0.w = v0.w * sc0 + sh0;
    o1.x = v1.x * sc1 + sh1; o1.y = v1.y * sc1 + sh1;
    o1.z = v1.z * sc1 + sh1; o1.w = v1.w * sc1 + sh1;
    ((float4*)out)[t] = o0;
    ((float4*)out)[t + 262144] = o1;
}

extern "C" void kernel_launch(void* const* d_in, const int* in_sizes, int n_in,
                              void* d_out, int out_size) {
    const float* x     = (const float*)d_in[0];
    const float* wr    = (const float*)d_in[1];
    const float* wi    = (const float*)d_in[2];
    const float* br    = (const float*)d_in[3];
    const float* bi    = (const float*)d_in[4];
    const float* cw    = (const float*)d_in[5];
    const float* cb    = (const float*)d_in[6];
    const float* gamma = (const float*)d_in[7];
    const float* beta  = (const float*)d_in[8];
    float* out = (float*)d_out;

    precompute_kernel<<<16, 1024>>>(wr, wi, br, bi, cw, cb);
    main_kernel<<<2048, 128>>>(x);
    stats_kernel<<<64, 256>>>(gamma, beta);
    finalize_kernel<<<512, 512>>>(out);
}

// round 16
// speedup vs baseline: 1.1354x; 1.0983x over previous
#include <cuda_runtime.h>
#include <cuda_bf16.h>
#include <math.h>
#include <stdint.h>

// ---------------------------------------------------------------------------
// CFNO folded: patchify(16x16) -> FFT(256) -> complex linear -> IFFT(16).real
// -> 1x1 conv == y = p @ G + g0 (real G[256][16]); then GroupNorm(8,16).
//
// Main kernel (best-measured config): HMMA m16n8k16 bf16, exact hi/lo split:
//   x = hi + lo (hi = fp32 top-16 bits, exact bf16; lo = x - hi)
//   y = Ah*Bh + Al*Bh + Ah*Bl   (AlBl ~2^-16 dropped)
// A gmem -> fragment registers (prefetch dist 2); B via smem uint4 LDS.
// ---------------------------------------------------------------------------

#define PI_D 3.141592653589793238462643383279502884

__device__ float g_g0[16];
__device__ __align__(16) uint2 g_Bfh[1024]; // B fragments hi: [kk][lane][nh]
__device__ __align__(16) uint2 g_Bfl[1024]; // B fragments lo
__device__ float g_Y[8 * 16 * 128 * 128];   // 8 MB, (b,e,h,w)
__device__ float g_psum[8 * 16 * 128];      // [b][e][hr]
__device__ float g_psq[8 * 16 * 128];

// ---------------------------------------------------------------------------
// Kernel 1: fold chain into B[256][16] and emit m16n8k16 B fragments.
// 1024 threads: DFT k-loop split 4 ways (ks = tid&3), shfl-quad reduce.
// Twiddles via float sincospi (error ~1e-7 << 1e-5 bf16-split floor).
// ---------------------------------------------------------------------------
__global__ void __launch_bounds__(1024) precompute_kernel(
        const float* __restrict__ wr, const float* __restrict__ wi,
        const float* __restrict__ br, const float* __restrict__ bi,
        const float* __restrict__ cw, const float* __restrict__ cb) {
    __shared__ float cosT[256], sinT[256];
    __shared__ float swr[16 * 257], swi[16 * 257];
    __shared__ float sCR[256], sCI[256];
    __shared__ float sMR[256], sMI[256];
    __shared__ float sB[256];
    const int tid = threadIdx.x;

    if (tid < 256) {
        float s, c;
        sincospif((float)tid * (2.0f / 256.0f), &s, &c);
        cosT[tid] = c; sinT[tid] = s;
    }
    for (int i = tid; i < 4096; i += 1024) {
        int d = i >> 8, k = i & 255;
        swr[d * 257 + k] = wr[i];
        swi[d * 257 + k] = wi[i];
    }
    __syncthreads();

    if (tid < 256) {   // CR/CI
        const int dd = tid >> 4, e = tid & 15;
        float cr = 0.f, ci = 0.f;
#pragma unroll
        for (int m = 0; m < 16; m++) {
            int t = ((dd * m) & 15) << 4;
            float w = cw[e * 16 + m];
            cr += w * cosT[t];
            ci += w * sinT[t];
        }
        sCR[dd * 16 + e] = cr; sCI[dd * 16 + e] = ci;
    }
    {   // MR/MI: jl = tid>>6, d = (tid>>2)&15, ks = tid&3
        const int jl = tid >> 6, d = (tid >> 2) & 15, ks = tid & 3;
        const int j = (blockIdx.x << 4) + jl;
        const float* a  = swr + d * 257;
        const float* bb = swi + d * 257;
        const int k0 = ks << 6;
        float mr0 = 0.f, mi0 = 0.f, mr1 = 0.f, mi1 = 0.f;
        float mr2 = 0.f, mi2 = 0.f, mr3 = 0.f, mi3 = 0.f;
        for (int k = k0; k < k0 + 64; k += 4) {
            int t0 = (k * j) & 255, t1 = (t0 + j) & 255;
            int t2 = (t1 + j) & 255, t3 = (t2 + j) & 255;
            float c0 = cosT[t0], s0 = sinT[t0], a0 = a[k],     b0 = bb[k];
            float c1 = cosT[t1], s1 = sinT[t1], a1 = a[k + 1], b1 = bb[k + 1];
            float c2 = cosT[t2], s2 = sinT[t2], a2 = a[k + 2], b2 = bb[k + 2];
            float c3 = cosT[t3], s3 = sinT[t3], a3 = a[k + 3], b3 = bb[k + 3];
            mr0 += a0 * c0 + b0 * s0;  mi0 += b0 * c0 - a0 * s0;
            mr1 += a1 * c1 + b1 * s1;  mi1 += b1 * c1 - a1 * s1;
            mr2 += a2 * c2 + b2 * s2;  mi2 += b2 * c2 - a2 * s2;
            mr3 += a3 * c3 + b3 * s3;  mi3 += b3 * c3 - a3 * s3;
        }
        float mr = (mr0 + mr1) + (mr2 + mr3);
        float mi = (mi0 + mi1) + (mi2 + mi3);
        mr += __shfl_xor_sync(0xffffffffu, mr, 1);
        mi += __shfl_xor_sync(0xffffffffu, mi, 1);
        mr += __shfl_xor_sync(0xffffffffu, mr, 2);
        mi += __shfl_xor_sync(0xffffffffu, mi, 2);
        if (ks == 0) { sMR[jl * 16 + d] = mr; sMI[jl * 16 + d] = mi; }
    }
    __syncthreads();
    if (tid < 256) {
        const int jl = tid >> 4, e = tid & 15;
        float g = 0.f;
#pragma unroll
        for (int d = 0; d < 16; d++)
            g += sMR[jl * 16 + d] * sCR[d * 16 + e] - sMI[jl * 16 + d] * sCI[d * 16 + e];
        sB[jl * 16 + e] = g * (1.0f / 64.0f);
    }
    __syncthreads();
    if (tid < 64) {   // emit fragments for kk = blockIdx.x; layout [kk][lane][nh]
        const int lane = tid & 31, nh = tid >> 5;
        const int q = lane & 3, gg = lane >> 2;
        const int n = nh * 8 + gg;
        const int j0 = 2 * q;
        float B0 = sB[(j0)     * 16 + n];
        float B1 = sB[(j0 + 1) * 16 + n];
        float B2 = sB[(j0 + 8) * 16 + n];
        float B3 = sB[(j0 + 9) * 16 + n];
        uint32_t u0 = __float_as_uint(B0), u1 = __float_as_uint(B1);
        uint32_t u2 = __float_as_uint(B2), u3 = __float_as_uint(B3);
        uint2 h, lo;
        h.x = __byte_perm(u0, u1, 0x7632);
        h.y = __byte_perm(u2, u3, 0x7632);
        float l0 = B0 - __uint_as_float(u0 & 0xFFFF0000u);
        float l1 = B1 - __uint_as_float(u1 & 0xFFFF0000u);
        float l2 = B2 - __uint_as_float(u2 & 0xFFFF0000u);
        float l3 = B3 - __uint_as_float(u3 & 0xFFFF0000u);
        asm("cvt.rn.bf16x2.f32 %0, %1, %2;" : "=r"(lo.x) : "f"(l1), "f"(l0));
        asm("cvt.rn.bf16x2.f32 %0, %1, %2;" : "=r"(lo.y) : "f"(l3), "f"(l2));
        const int t = (blockIdx.x << 6) + lane * 2 + nh;
        g_Bfh[t] = h;
        g_Bfl[t] = lo;
    }
    if (blockIdx.x == 0 && tid < 16) {
        float acc = cb[tid];
        for (int m = 0; m < 16; m++) {
            float b0 = 0.f;
            for (int d = 0; d < 16; d++) {
                int t = ((d * m) & 15) << 4;
                b0 += br[d] * cosT[t] - bi[d] * sinT[t];
            }
            acc += cw[tid * 16 + m] * b0 * 0.25f;
        }
        g_g0[tid] = acc;
    }
}

// ---------------------------------------------------------------------------
// Main kernel helpers
// ---------------------------------------------------------------------------
__device__ __forceinline__ void split_bf16(float2 f, uint32_t& h, uint32_t& lo) {
    uint32_t u0 = __float_as_uint(f.x), u1 = __float_as_uint(f.y);
    h = __byte_perm(u0, u1, 0x7632);
    float l0 = f.x - __uint_as_float(u0 & 0xFFFF0000u);
    float l1 = f.y - __uint_as_float(u1 & 0xFFFF0000u);
    asm("cvt.rn.bf16x2.f32 %0, %1, %2;" : "=r"(lo) : "f"(l1), "f"(l0));
}
__device__ __forceinline__ void mma16816(float* c, const uint32_t* a, uint32_t bx, uint32_t by) {
    asm("mma.sync.aligned.m16n8k16.row.col.f32.bf16.bf16.f32 "
        "{%0,%1,%2,%3}, {%4,%5,%6,%7}, {%8,%9}, {%0,%1,%2,%3};"
        : "+f"(c[0]), "+f"(c[1]), "+f"(c[2]), "+f"(c[3])
        : "r"(a[0]), "r"(a[1]), "r"(a[2]), "r"(a[3]), "r"(bx), "r"(by));
}

// ---------------------------------------------------------------------------
// Kernel 2 (hot): 1024 blocks x 256 threads (8 warps). Block = one patch row;
// warp = 16 patches. A gmem -> fragment registers, prefetch distance 2;
// B via smem, 2x LDS.128 per k-step. (Best-measured configuration.)
// ---------------------------------------------------------------------------
#define SYP 132

__global__ void __launch_bounds__(256) main_kernel(const float* __restrict__ x) {
    __shared__ uint2 sBh[1024];
    __shared__ uint2 sBl[1024];
    __shared__ float sY[16 * SYP];
    const int tid = threadIdx.x;
    const int w = tid >> 5, lane = tid & 31;
    const int b  = blockIdx.x >> 7;
    const int hr = blockIdx.x & 127;

#pragma unroll
    for (int u = 0; u < 4; u++) {
        sBh[tid + (u << 8)] = g_Bfh[tid + (u << 8)];
        sBl[tid + (u << 8)] = g_Bfl[tid + (u << 8)];
    }
    __syncthreads();

    const int g = lane >> 2, q = lane & 3;
    const float* aptr = x + (((size_t)b) << 22) + (((size_t)hr) << 15)
                          + (w * 16 + g) * 16 + q * 2;

    float acc0[4] = {0.f, 0.f, 0.f, 0.f};
    float acc1[4] = {0.f, 0.f, 0.f, 0.f};

    float2 f[2][4];
#pragma unroll
    for (int p = 0; p < 2; p++) {
        const float* rp = aptr + (p << 11);
        f[p][0] = *(const float2*)(rp);
        f[p][1] = *(const float2*)(rp + 8);
        f[p][2] = *(const float2*)(rp + 128);
        f[p][3] = *(const float2*)(rp + 136);
    }

#pragma unroll
    for (int kk = 0; kk < 16; kk++) {
        const int cur = kk & 1;
        uint32_t ah[4], al[4];
        split_bf16(f[cur][0], ah[0], al[0]);   // row g,   k-low
        split_bf16(f[cur][2], ah[1], al[1]);   // row g+8, k-low
        split_bf16(f[cur][1], ah[2], al[2]);   // row g,   k-high
        split_bf16(f[cur][3], ah[3], al[3]);   // row g+8, k-high

        if (kk < 14) {
            const float* np = aptr + ((kk + 2) << 11);
            f[cur][0] = *(const float2*)(np);
            f[cur][1] = *(const float2*)(np + 8);
            f[cur][2] = *(const float2*)(np + 128);
            f[cur][3] = *(const float2*)(np + 136);
        }

        uint4 vh = ((const uint4*)sBh)[(kk << 5) + lane];
        uint4 vl = ((const uint4*)sBl)[(kk << 5) + lane];
        uint2 bh0 = make_uint2(vh.x, vh.y), bh1 = make_uint2(vh.z, vh.w);
        uint2 bl0 = make_uint2(vl.x, vl.y), bl1 = make_uint2(vl.z, vl.w);

        mma16816(acc0, ah, bh0.x, bh0.y);
        mma16816(acc1, ah, bh1.x, bh1.y);
        mma16816(acc0, al, bh0.x, bh0.y);
        mma16816(acc1, al, bh1.x, bh1.y);
        mma16816(acc0, ah, bl0.x, bl0.y);
        mma16816(acc1, ah, bl1.x, bl1.y);
    }

    // scatter C fragments to sY[e][p]
    {
        const int p_lo = w * 16 + g, p_hi = p_lo + 8;
        sY[(2 * q + 0) * SYP + p_lo] = acc0[0];
        sY[(2 * q + 1) * SYP + p_lo] = acc0[1];
        sY[(2 * q + 0) * SYP + p_hi] = acc0[2];
        sY[(2 * q + 1) * SYP + p_hi] = acc0[3];
        sY[(8 + 2 * q) * SYP + p_lo] = acc1[0];
        sY[(9 + 2 * q) * SYP + p_lo] = acc1[1];
        sY[(8 + 2 * q) * SYP + p_hi] = acc1[2];
        sY[(9 + 2 * q) * SYP + p_hi] = acc1[3];
    }
    __syncthreads();

    // staging: thread -> channel e = tid>>4, 8 consecutive patches
    {
        const int e = tid >> 4, i2 = tid & 15;
        const float g0v = g_g0[e];
        float v[8];
        float4 va = *(const float4*)&sY[e * SYP + i2 * 8];
        float4 vb = *(const float4*)&sY[e * SYP + i2 * 8 + 4];
        v[0] = va.x + g0v; v[1] = va.y + g0v; v[2] = va.z + g0v; v[3] = va.w + g0v;
        v[4] = vb.x + g0v; v[5] = vb.y + g0v; v[6] = vb.z + g0v; v[7] = vb.w + g0v;

        float s = 0.f, qq = 0.f;
#pragma unroll
        for (int j = 0; j < 8; j++) { s += v[j]; qq += v[j] * v[j]; }

        float* dst = &g_Y[(((size_t)(b * 16 + e)) << 14) + (hr << 7) + i2 * 8];
        *(float4*)dst = make_float4(v[0], v[1], v[2], v[3]);
        *(float4*)(dst + 4) = make_float4(v[4], v[5], v[6], v[7]);

#pragma unroll
        for (int off = 8; off; off >>= 1) {
            s  += __shfl_down_sync(0xffffffffu, s, off, 16);
            qq += __shfl_down_sync(0xffffffffu, qq, off, 16);
        }
        if (i2 == 0) {
            g_psum[(b * 16 + e) * 128 + hr] = s;
            g_psq[(b * 16 + e) * 128 + hr] = qq;
        }
    }
}

// ---------------------------------------------------------------------------
// Kernel 3 (fused stats+normalize): 512 blocks x 256 threads.
// Block = (plane = bid>>2, quarter = bid&3). Each block redundantly reduces
// its group's 2x128 partials (coalesced), computes scale/shift, then
// normalizes its quarter-plane (4 coalesced float4 per thread).
// ---------------------------------------------------------------------------
__global__ void __launch_bounds__(256) finalize_kernel(const float* __restrict__ gamma,
                                                       const float* __restrict__ beta,
                                                       float* __restrict__ out) {
    __shared__ float ss[8], sq[8];
    __shared__ float s_sc, s_sh;
    const int plane = blockIdx.x >> 2;      // b*16 + e
    const int quar  = blockIdx.x & 3;
    const int b = plane >> 4, e = plane & 15;
    const int e0 = e & ~1;
    const int tid = threadIdx.x;

    {   // group stats: channels e0, e0+1; 128 slots each
        const int ch = tid >> 7, slot = tid & 127;
        const int base = (b * 16 + e0 + ch) * 128 + slot;
        float s = g_psum[base];
        float q = g_psq[base];
#pragma unroll
        for (int off = 16; off; off >>= 1) {
            s += __shfl_down_sync(0xffffffffu, s, off);
            q += __shfl_down_sync(0xffffffffu, q, off);
        }
        const int lane = tid & 31, wrp = tid >> 5;
        if (lane == 0) { ss[wrp] = s; sq[wrp] = q; }
    }
    __syncthreads();
    if (tid == 0) {
        float st = 0.f, qt = 0.f;
#pragma unroll
        for (int k = 0; k < 8; k++) { st += ss[k]; qt += sq[k]; }
        const float invN = 1.0f / 32768.0f;
        float mean = st * invN;
        float var  = qt * invN - mean * mean;
        float istd = rsqrtf(var + 1e-5f);
        float sc = istd * gamma[e];
        s_sc = sc;
        s_sh = beta[e] - mean * sc;
    }
    __syncthreads();

    const float sc = s_sc, sh = s_sh;
    const int base4 = (plane << 12) + (quar << 10);       // float4 units
#pragma unroll
    for (int j = 0; j < 4; j++) {
        const int idx = base4 + (j << 8) + tid;
        float4 v = ((const float4*)g_Y)[idx];
        v.x = v.x * sc + sh; v.y = v.y * sc + sh;
        v.z = v.z * sc + sh; v.w = v.w * sc + sh;
        ((float4*)out)[idx] = v;
    }
}

extern "C" void kernel_launch(void* const* d_in, const int* in_sizes, int n_in,
                              void* d_out, int out_size) {
    const float* x     = (const float*)d_in[0];
    const float* wr    = (const float*)d_in[1];
    const float* wi    = (const float*)d_in[2];
    const float* br    = (const float*)d_in[3];
    const float* bi    = (const float*)d_in[4];
    const float* cw    = (const float*)d_in[5];
    const float* cb    = (const float*)d_in[6];
    const float* gamma = (const float*)d_in[7];
    const float* beta  = (const float*)d_in[8];
    float* out = (float*)d_out;

    precompute_kernel<<<16, 1024>>>(wr, wi, br, bi, cw, cb);
    main_kernel<<<1024, 256>>>(x);
    finalize_kernel<<<512, 256>>>(gamma, beta, out);
}

// round 17
// speedup vs baseline: 1.3203x; 1.1628x over previous
#include <cuda_runtime.h>
#include <cuda_bf16.h>
#include <math.h>
#include <stdint.h>

// ---------------------------------------------------------------------------
// CFNO folded: patchify(16x16) -> FFT(256) -> complex linear -> IFFT(16).real
// -> 1x1 conv == y = p @ G + g0 (real G[256][16]); then GroupNorm(8,16).
//
// Main kernel (best-measured config): HMMA m16n8k16 bf16, exact hi/lo split:
//   x = hi + lo (hi = fp32 top-16 bits, exact bf16; lo = x - hi)
//   y = Ah*Bh + Al*Bh + Ah*Bl   (AlBl ~2^-16 dropped)
// A gmem -> fragment registers (prefetch dist 2); B via smem uint4 LDS.
// Precompute parallelized: 256 blocks (one B row each) + tiny fragment kernel.
// ---------------------------------------------------------------------------

__device__ float g_g0[16];
__device__ float g_B[4096];                 // [256 k][16 e] folded matrix
__device__ __align__(16) uint2 g_Bfh[1024]; // B fragments hi: [kk][lane][nh]
__device__ __align__(16) uint2 g_Bfl[1024]; // B fragments lo
__device__ float g_Y[8 * 16 * 128 * 128];   // 8 MB, (b,e,h,w)
__device__ float g_psum[8 * 16 * 128];      // [b][e][hr]
__device__ float g_psq[8 * 16 * 128];

// ---------------------------------------------------------------------------
// Kernel 1: fold chain into B[256][16]. 256 blocks x 256 threads.
// Block r computes B row r: thread (d = tid>>4, ks = tid&15) sums 16 DFT
// terms; width-16 shfl reduce -> MR/MI[d]; 16 threads contract with CR/CI.
// ---------------------------------------------------------------------------
__global__ void __launch_bounds__(256) precompute_kernel(
        const float* __restrict__ wr, const float* __restrict__ wi,
        const float* __restrict__ cw) {
    __shared__ float cosT[256], sinT[256];
    __shared__ float sCR[256], sCI[256];
    __shared__ float sMR[16], sMI[16];
    const int tid = threadIdx.x;
    const int r = blockIdx.x;

    {
        float s, c;
        sincospif((float)tid * (2.0f / 256.0f), &s, &c);
        cosT[tid] = c; sinT[tid] = s;
    }
    __syncthreads();

    {   // CR/CI: dd = tid>>4, e = tid&15
        const int dd = tid >> 4, e = tid & 15;
        float cr = 0.f, ci = 0.f;
#pragma unroll
        for (int m = 0; m < 16; m++) {
            int t = ((dd * m) & 15) << 4;
            float w = cw[e * 16 + m];
            cr += w * cosT[t];
            ci += w * sinT[t];
        }
        sCR[dd * 16 + e] = cr; sCI[dd * 16 + e] = ci;
    }
    {   // MR/MI row r: d = tid>>4, k-slice ks = tid&15 (16 terms each)
        const int d = tid >> 4, ks = tid & 15;
        const float* wrp = wr + d * 256 + ks * 16;
        const float* wip = wi + d * 256 + ks * 16;
        int t = (r * ks * 16) & 255;
        float mr = 0.f, mi = 0.f;
#pragma unroll
        for (int i = 0; i < 16; i++) {
            float c = cosT[t], s = sinT[t];
            float av = wrp[i], bv = wip[i];
            mr += av * c + bv * s;
            mi += bv * c - av * s;
            t = (t + r) & 255;
        }
#pragma unroll
        for (int off = 8; off; off >>= 1) {
            mr += __shfl_xor_sync(0xffffffffu, mr, off, 16);
            mi += __shfl_xor_sync(0xffffffffu, mi, off, 16);
        }
        if (ks == 0) { sMR[d] = mr; sMI[d] = mi; }
    }
    __syncthreads();
    if (tid < 16) {   // B[r][e]
        const int e = tid;
        float g = 0.f;
#pragma unroll
        for (int d = 0; d < 16; d++)
            g += sMR[d] * sCR[d * 16 + e] - sMI[d] * sCI[d * 16 + e];
        g_B[r * 16 + e] = g * (1.0f / 64.0f);
    }
}

// ---------------------------------------------------------------------------
// Kernel 1b: emit m16n8k16 B fragments (hi/lo split) + bias g0.
// 1 block x 1024 threads; one fragment pair per thread, B read via L2.
// ---------------------------------------------------------------------------
__global__ void __launch_bounds__(1024) bfrag_kernel(
        const float* __restrict__ br, const float* __restrict__ bi,
        const float* __restrict__ cw, const float* __restrict__ cb) {
    __shared__ float cos16[16], sin16[16];
    const int t = threadIdx.x;
    if (t < 16) {
        float s, c;
        sincospif((float)t * 0.125f, &s, &c);
        cos16[t] = c; sin16[t] = s;
    }
    {
        const int kk = t >> 6, r6 = t & 63;
        const int nh = r6 >> 5, lane = r6 & 31;
        const int q = lane & 3, g = lane >> 2;
        const int n = nh * 8 + g;
        const int k0 = kk * 16 + 2 * q;
        float B0 = g_B[(k0)     * 16 + n];
        float B1 = g_B[(k0 + 1) * 16 + n];
        float B2 = g_B[(k0 + 8) * 16 + n];
        float B3 = g_B[(k0 + 9) * 16 + n];
        uint32_t u0 = __float_as_uint(B0), u1 = __float_as_uint(B1);
        uint32_t u2 = __float_as_uint(B2), u3 = __float_as_uint(B3);
        uint2 h, lo;
        h.x = __byte_perm(u0, u1, 0x7632);
        h.y = __byte_perm(u2, u3, 0x7632);
        float l0 = B0 - __uint_as_float(u0 & 0xFFFF0000u);
        float l1 = B1 - __uint_as_float(u1 & 0xFFFF0000u);
        float l2 = B2 - __uint_as_float(u2 & 0xFFFF0000u);
        float l3 = B3 - __uint_as_float(u3 & 0xFFFF0000u);
        asm("cvt.rn.bf16x2.f32 %0, %1, %2;" : "=r"(lo.x) : "f"(l1), "f"(l0));
        asm("cvt.rn.bf16x2.f32 %0, %1, %2;" : "=r"(lo.y) : "f"(l3), "f"(l2));
        const int idx = (kk << 6) + lane * 2 + nh;
        g_Bfh[idx] = h;
        g_Bfl[idx] = lo;
    }
    __syncthreads();
    if (t < 16) {
        float acc = cb[t];
        for (int m = 0; m < 16; m++) {
            float b0 = 0.f;
            for (int d = 0; d < 16; d++) {
                int a = (d * m) & 15;
                b0 += br[d] * cos16[a] - bi[d] * sin16[a];
            }
            acc += cw[t * 16 + m] * b0 * 0.25f;
        }
        g_g0[t] = acc;
    }
}

// ---------------------------------------------------------------------------
// Main kernel helpers
// ---------------------------------------------------------------------------
__device__ __forceinline__ void split_bf16(float2 f, uint32_t& h, uint32_t& lo) {
    uint32_t u0 = __float_as_uint(f.x), u1 = __float_as_uint(f.y);
    h = __byte_perm(u0, u1, 0x7632);
    float l0 = f.x - __uint_as_float(u0 & 0xFFFF0000u);
    float l1 = f.y - __uint_as_float(u1 & 0xFFFF0000u);
    asm("cvt.rn.bf16x2.f32 %0, %1, %2;" : "=r"(lo) : "f"(l1), "f"(l0));
}
__device__ __forceinline__ void mma16816(float* c, const uint32_t* a, uint32_t bx, uint32_t by) {
    asm("mma.sync.aligned.m16n8k16.row.col.f32.bf16.bf16.f32 "
        "{%0,%1,%2,%3}, {%4,%5,%6,%7}, {%8,%9}, {%0,%1,%2,%3};"
        : "+f"(c[0]), "+f"(c[1]), "+f"(c[2]), "+f"(c[3])
        : "r"(a[0]), "r"(a[1]), "r"(a[2]), "r"(a[3]), "r"(bx), "r"(by));
}

// ---------------------------------------------------------------------------
// Kernel 2 (hot): 1024 blocks x 256 threads (8 warps). Block = one patch row;
// warp = 16 patches. A gmem -> fragment registers, prefetch distance 2;
// B via smem, 2x LDS.128 per k-step. (Best-measured configuration.)
// ---------------------------------------------------------------------------
#define SYP 132

__global__ void __launch_bounds__(256) main_kernel(const float* __restrict__ x) {
    __shared__ uint2 sBh[1024];
    __shared__ uint2 sBl[1024];
    __shared__ float sY[16 * SYP];
    const int tid = threadIdx.x;
    const int w = tid >> 5, lane = tid & 31;
    const int b  = blockIdx.x >> 7;
    const int hr = blockIdx.x & 127;

#pragma unroll
    for (int u = 0; u < 4; u++) {
        sBh[tid + (u << 8)] = g_Bfh[tid + (u << 8)];
        sBl[tid + (u << 8)] = g_Bfl[tid + (u << 8)];
    }
    __syncthreads();

    const int g = lane >> 2, q = lane & 3;
    const float* aptr = x + (((size_t)b) << 22) + (((size_t)hr) << 15)
                          + (w * 16 + g) * 16 + q * 2;

    float acc0[4] = {0.f, 0.f, 0.f, 0.f};
    float acc1[4] = {0.f, 0.f, 0.f, 0.f};

    float2 f[2][4];
#pragma unroll
    for (int p = 0; p < 2; p++) {
        const float* rp = aptr + (p << 11);
        f[p][0] = *(const float2*)(rp);
        f[p][1] = *(const float2*)(rp + 8);
        f[p][2] = *(const float2*)(rp + 128);
        f[p][3] = *(const float2*)(rp + 136);
    }

#pragma unroll
    for (int kk = 0; kk < 16; kk++) {
        const int cur = kk & 1;
        uint32_t ah[4], al[4];
        split_bf16(f[cur][0], ah[0], al[0]);   // row g,   k-low
        split_bf16(f[cur][2], ah[1], al[1]);   // row g+8, k-low
        split_bf16(f[cur][1], ah[2], al[2]);   // row g,   k-high
        split_bf16(f[cur][3], ah[3], al[3]);   // row g+8, k-high

        if (kk < 14) {
            const float* np = aptr + ((kk + 2) << 11);
            f[cur][0] = *(const float2*)(np);
            f[cur][1] = *(const float2*)(np + 8);
            f[cur][2] = *(const float2*)(np + 128);
            f[cur][3] = *(const float2*)(np + 136);
        }

        uint4 vh = ((const uint4*)sBh)[(kk << 5) + lane];
        uint4 vl = ((const uint4*)sBl)[(kk << 5) + lane];

        mma16816(acc0, ah, vh.x, vh.y);
        mma16816(acc1, ah, vh.z, vh.w);
        mma16816(acc0, al, vh.x, vh.y);
        mma16816(acc1, al, vh.z, vh.w);
        mma16816(acc0, ah, vl.x, vl.y);
        mma16816(acc1, ah, vl.z, vl.w);
    }

    // scatter C fragments to sY[e][p]
    {
        const int p_lo = w * 16 + g, p_hi = p_lo + 8;
        sY[(2 * q + 0) * SYP + p_lo] = acc0[0];
        sY[(2 * q + 1) * SYP + p_lo] = acc0[1];
        sY[(2 * q + 0) * SYP + p_hi] = acc0[2];
        sY[(2 * q + 1) * SYP + p_hi] = acc0[3];
        sY[(8 + 2 * q) * SYP + p_lo] = acc1[0];
        sY[(9 + 2 * q) * SYP + p_lo] = acc1[1];
        sY[(8 + 2 * q) * SYP + p_hi] = acc1[2];
        sY[(9 + 2 * q) * SYP + p_hi] = acc1[3];
    }
    __syncthreads();

    // staging: thread -> channel e = tid>>4, 8 consecutive patches
    {
        const int e = tid >> 4, i2 = tid & 15;
        const float g0v = g_g0[e];
        float v[8];
        float4 va = *(const float4*)&sY[e * SYP + i2 * 8];
        float4 vb = *(const float4*)&sY[e * SYP + i2 * 8 + 4];
        v[0] = va.x + g0v; v[1] = va.y + g0v; v[2] = va.z + g0v; v[3] = va.w + g0v;
        v[4] = vb.x + g0v; v[5] = vb.y + g0v; v[6] = vb.z + g0v; v[7] = vb.w + g0v;

        float s = 0.f, qq = 0.f;
#pragma unroll
        for (int j = 0; j < 8; j++) { s += v[j]; qq += v[j] * v[j]; }

        float* dst = &g_Y[(((size_t)(b * 16 + e)) << 14) + (hr << 7) + i2 * 8];
        *(float4*)dst = make_float4(v[0], v[1], v[2], v[3]);
        *(float4*)(dst + 4) = make_float4(v[4], v[5], v[6], v[7]);

#pragma unroll
        for (int off = 8; off; off >>= 1) {
            s  += __shfl_down_sync(0xffffffffu, s, off, 16);
            qq += __shfl_down_sync(0xffffffffu, qq, off, 16);
        }
        if (i2 == 0) {
            g_psum[(b * 16 + e) * 128 + hr] = s;
            g_psq[(b * 16 + e) * 128 + hr] = qq;
        }
    }
}

// ---------------------------------------------------------------------------
// Kernel 3 (fused stats+normalize): 512 blocks x 256 threads.
// Block = (plane = bid>>2, quarter = bid&3). Each block redundantly reduces
// its group's 2x128 partials, computes scale/shift, normalizes its quarter.
// ---------------------------------------------------------------------------
__global__ void __launch_bounds__(256) finalize_kernel(const float* __restrict__ gamma,
                                                       const float* __restrict__ beta,
                                                       float* __restrict__ out) {
    __shared__ float ss[8], sq[8];
    __shared__ float s_sc, s_sh;
    const int plane = blockIdx.x >> 2;      // b*16 + e
    const int quar  = blockIdx.x & 3;
    const int b = plane >> 4, e = plane & 15;
    const int e0 = e & ~1;
    const int tid = threadIdx.x;

    {
        const int ch = tid >> 7, slot = tid & 127;
        const int base = (b * 16 + e0 + ch) * 128 + slot;
        float s = g_psum[base];
        float q = g_psq[base];
#pragma unroll
        for (int off = 16; off; off >>= 1) {
            s += __shfl_down_sync(0xffffffffu, s, off);
            q += __shfl_down_sync(0xffffffffu, q, off);
        }
        const int lane = tid & 31, wrp = tid >> 5;
        if (lane == 0) { ss[wrp] = s; sq[wrp] = q; }
    }
    __syncthreads();
    if (tid == 0) {
        float st = 0.f, qt = 0.f;
#pragma unroll
        for (int k = 0; k < 8; k++) { st += ss[k]; qt += sq[k]; }
        const float invN = 1.0f / 32768.0f;
        float mean = st * invN;
        float var  = qt * invN - mean * mean;
        float istd = rsqrtf(var + 1e-5f);
        float sc = istd * gamma[e];
        s_sc = sc;
        s_sh = beta[e] - mean * sc;
    }
    __syncthreads();

    const float sc = s_sc, sh = s_sh;
    const int base4 = (plane << 12) + (quar << 10);       // float4 units
#pragma unroll
    for (int j = 0; j < 4; j++) {
        const int idx = base4 + (j << 8) + tid;
        float4 v = ((const float4*)g_Y)[idx];
        v.x = v.x * sc + sh; v.y = v.y * sc + sh;
        v.z = v.z * sc + sh; v.w = v.w * sc + sh;
        ((float4*)out)[idx] = v;
    }
}

extern "C" void kernel_launch(void* const* d_in, const int* in_sizes, int n_in,
                              void* d_out, int out_size) {
    const float* x     = (const float*)d_in[0];
    const float* wr    = (const float*)d_in[1];
    const float* wi    = (const float*)d_in[2];
    const float* br    = (const float*)d_in[3];
    const float* bi    = (const float*)d_in[4];
    const float* cw    = (const float*)d_in[5];
    const float* cb    = (const float*)d_in[6];
    const float* gamma = (const float*)d_in[7];
    const float* beta  = (const float*)d_in[8];
    float* out = (float*)d_out;

    precompute_kernel<<<256, 256>>>(wr, wi, cw);
    bfrag_kernel<<<1, 1024>>>(br, bi, cw, cb);
    main_kernel<<<1024, 256>>>(x);
    finalize_kernel<<<512, 256>>>(gamma, beta, out);
}